// round 11
// baseline (speedup 1.0000x reference)
#include <cuda_runtime.h>
#include <cstdint>

#define T_STEPS 16384
#define RING 6
#define FULLMASK 0xffffffffu

// Per-step blob, 52 floats per lane (32 lanes) = 1664 floats = 6656 B/step.
// Lane L (n = L&15, hi = L>=16):
//  f[0..15]  : A[n][m], m=0..15      (full row, duplicated across halves)
//  f[16..31] : K1 col n (lo) / K3 col n (hi)
//  f[32..47] : K5[m][n], m=0..15     (full column, duplicated across halves)
//  f[48]     : u0[n] (lo) / u2[n] (hi)
//  f[49]     : bh[n]  (full, both halves)
//  f[50]     : u4[n]  (full, both halves)
//  f[51]     : pad
// Storage: blob[t][g][L] as float4, g = f>>2 (0..12), L = 0..31.
__device__ float g_blob[(size_t)T_STEPS * 1664];

#define BIDX(ln, f) ((((f) >> 2) * 128) + ((ln) * 4) + ((f) & 3))

__device__ __forceinline__ float tanha(float x){
    float y; asm("tanh.approx.f32 %0, %1;" : "=f"(y) : "f"(x)); return y;
}
__device__ __forceinline__ float sigm(float x){ return fmaf(0.5f, tanha(0.5f * x), 0.5f); }

// ---------------------------------------------------------------------------
// Precompute kernel: one warp per timestep.
// ---------------------------------------------------------------------------
__global__ void __launch_bounds__(128) precompute_kernel(
    const float* __restrict__ inputs, const float* __restrict__ a_list,
    const float* __restrict__ gcn_wx, const float* __restrict__ gcn_bx,
    const float* __restrict__ gcn_wh, const float* __restrict__ gcn_bh,
    const float* __restrict__ gru_k,  const float* __restrict__ gru_b)
{
    __shared__ float Lh[3][16][16];
    __shared__ float Lsum[16][16];
    __shared__ float dd[3][16], dis[3][16];
    __shared__ float Qh[4][256];
    __shared__ float bs[4][1664];
    __shared__ float xsc[4][80];

    int tid = threadIdx.x;

    if (tid < 48) {
        int l = tid / 16, j = tid % 16;
        float s = 0.0f;
        #pragma unroll
        for (int i = 0; i < 16; i++) s += a_list[l*256 + i*16 + j];
        dd[l][j] = s;
        dis[l][j] = rsqrtf(s);
    }
    __syncthreads();
    for (int e = tid; e < 768; e += 128) {
        int l = e / 256, rc = e % 256, i = rc / 16, j = rc % 16;
        float Lv = ((i == j) ? dd[l][i] : 0.0f) - a_list[e];
        Lh[l][i][j] = Lv * dis[l][i] * dis[l][j];
    }
    __syncthreads();
    {
        float* LsF = &Lsum[0][0];
        float* LhF = &Lh[0][0][0];
        for (int e = tid; e < 256; e += 128)
            LsF[e] = LhF[e] + LhF[256 + e] + LhF[512 + e];
    }
    __syncthreads();

    int w = tid >> 5, lane = tid & 31;
    int t = blockIdx.x * 4 + w;

    float* LsF = &Lsum[0][0];
    float* LhF = &Lh[0][0][0];

    // zero staging
    for (int i = lane; i < 1664; i += 32) bs[w][i] = 0.0f;
    __syncwarp();

    // ---- h-GCN matrix A (full rows, both halves) ----
    const float* wh = gcn_wh + t * 13;
    float wh0 = wh[0], wh1 = wh[1], wh2 = wh[2];
    float wh10 = wh[10], wh11 = wh[11], wh12 = wh[12];

    for (int e = lane; e < 256; e += 32)
        Qh[w][e] = wh0*LhF[e] + wh1*LhF[256+e] + wh2*LhF[512+e];
    __syncwarp();

    float cA1 = wh0 * wh11, cA2 = wh0 * wh12;
    for (int e = lane; e < 256; e += 32) {
        int n = e >> 4, m = e & 15;
        float ql = 0.0f;
        #pragma unroll
        for (int k = 0; k < 16; k++) ql += Qh[w][n*16 + k] * LsF[k*16 + m];
        float Av = ((n == m) ? wh10 : 0.0f) + cA1 * LsF[e] + cA2 * ql;
        if (t == 0) Av = 0.0f;
        bs[w][BIDX(n, m)] = Av;
        bs[w][BIDX(16 + n, m)] = Av;
    }

    // ---- x-GCN -> xg ----
    const float* wx  = gcn_wx + t * 26;
    const float* xin = inputs + t * 32;
    {
        int c = lane >> 4, k = lane & 15;
        float s = 0.0f;
        #pragma unroll
        for (int m = 0; m < 16; m++) s += LsF[k*16 + m] * xin[m*2 + c];
        xsc[w][lane] = s;
    }
    __syncwarp();
    {
        int c = lane >> 4, n = lane & 15;
        float wc0 = wx[c*13], wc1 = wx[c*13 + 1], wc2 = wx[c*13 + 2];
        float g = 0.0f;
        #pragma unroll
        for (int k = 0; k < 16; k++)
            g += (wc0*Lh[0][n][k] + wc1*Lh[1][n][k] + wc2*Lh[2][n][k]) * xsc[w][c*16 + k];
        float part = wx[c*13 + 10] * xin[n*2 + c]
                   + wx[c*13 + 11] * wc0 * xsc[w][c*16 + n]
                   + wx[c*13 + 12] * wc0 * g;
        xsc[w][32 + lane] = part;
    }
    __syncwarp();
    if (lane < 16) {
        float xg = xsc[w][32 + lane] + xsc[w][48 + lane] + gcn_bx[t*16 + lane];
        xsc[w][64 + lane] = fmaxf(xg, 0.0f);
    }
    __syncwarp();

    // ---- u vectors ----
    const float* gk = gru_k + (size_t)t * 1536;
    const float* gb = gru_b + t * 96;
    for (int e = lane; e < 48; e += 32) {
        int i2 = e >> 4, j = e & 15;
        const float* Kb = gk + i2 * 512;
        float u = gb[i2*32 + j] + gb[i2*32 + 16 + j];
        #pragma unroll
        for (int m = 0; m < 16; m++) u += xsc[w][64 + m] * Kb[m*16 + j];
        if (i2 == 0)      bs[w][BIDX(j, 48)] = u;
        else if (i2 == 1) bs[w][BIDX(16 + j, 48)] = u;
        else { bs[w][BIDX(j, 50)] = u; bs[w][BIDX(16 + j, 50)] = u; }
    }

    // ---- K1/K3 columns (per half) + K5 full columns (both halves) ----
    for (int e = lane; e < 768; e += 32) {
        int which = e >> 8, rc = e & 255, m = rc >> 4, nn = rc & 15;
        float kv = gk[(2*which + 1)*256 + m*16 + nn];
        if (which == 0)      bs[w][BIDX(nn, 16 + m)] = kv;
        else if (which == 1) bs[w][BIDX(16 + nn, 16 + m)] = kv;
        else { bs[w][BIDX(nn, 32 + m)] = kv; bs[w][BIDX(16 + nn, 32 + m)] = kv; }
    }

    // ---- bh (full, both halves) ----
    if (lane < 16) {
        float bh = (t == 0) ? 0.0f : gcn_bh[t*16 + lane];
        bs[w][BIDX(lane, 49)] = bh;
        bs[w][BIDX(16 + lane, 49)] = bh;
    }
    __syncwarp();

    float4* dst = reinterpret_cast<float4*>(g_blob + (size_t)t * 1664);
    const float4* srcv = reinterpret_cast<const float4*>(bs[w]);
    for (int i = lane; i < 416; i += 32) dst[i] = srcv[i];
}

// ---------------------------------------------------------------------------
// Recurrence kernel
// ---------------------------------------------------------------------------
__device__ __forceinline__ int ldacq(uint32_t a){
    int v; asm volatile("ld.acquire.cta.shared::cta.b32 %0, [%1];" : "=r"(v) : "r"(a)); return v;
}

// Predicated global store: no BSSY/BSYNC.
__device__ __forceinline__ void st_pred(float* p, float v, uint32_t pred){
    asm volatile("{\n\t.reg .pred q;\n\tsetp.ne.u32 q, %2, 0;\n\t@q st.global.f32 [%0], %1;\n\t}"
                 :: "l"(p), "f"(v), "r"(pred) : "memory");
}

__device__ __forceinline__ void sts_f32(uint32_t a, float v){
    asm volatile("st.volatile.shared.f32 [%0], %1;" :: "r"(a), "f"(v));
}
__device__ __forceinline__ void lds_v4(float* d, uint32_t a){
    asm volatile("ld.volatile.shared.v4.f32 {%0,%1,%2,%3}, [%4];"
                 : "=f"(d[0]),"=f"(d[1]),"=f"(d[2]),"=f"(d[3]) : "r"(a));
}

// Full-width dots per lane: no cross-half xor reductions at all.
// All inter-lane traffic via smem exchanges (converged warp, in-order LSU).
__device__ __forceinline__ void gru_step(const float (&w)[52], float (&hv)[16],
                                         float* __restrict__ out, int t,
                                         uint32_t hip,
                                         uint32_t hgb, uint32_t hgslot,
                                         uint32_t rhb, uint32_t rhslot,
                                         uint32_t hb,  uint32_t hslot)
{
    // hg = relu(A@h + bh), full 16-wide dot, 4 chains, bh folded
    float a0 = fmaf(w[0], hv[0], w[49]);
    float a1 = w[1]*hv[1];
    float a2 = w[2]*hv[2];
    float a3 = w[3]*hv[3];
    #pragma unroll
    for (int m = 4; m < 16; m += 4) {
        a0 = fmaf(w[m],   hv[m],   a0);
        a1 = fmaf(w[m+1], hv[m+1], a1);
        a2 = fmaf(w[m+2], hv[m+2], a2);
        a3 = fmaf(w[m+3], hv[m+3], a3);
    }
    float hg = fmaxf((a0 + a1) + (a2 + a3), 0.0f);

    // hg exchange: 1 STS + 4 LDS.128 (lanes n and n+16 write same value)
    float hgv[16];
    sts_f32(hgslot, hg);
    lds_v4(hgv + 0,  hgb);
    lds_v4(hgv + 4,  hgb + 16);
    lds_v4(hgv + 8,  hgb + 32);
    lds_v4(hgv + 12, hgb + 48);

    // r (lo) / z (hi) dot, 4 chains, u folded
    float v0 = fmaf(hgv[0], w[16], w[48]);
    float v1 = hgv[1]*w[17];
    float v2 = hgv[2]*w[18];
    float v3 = hgv[3]*w[19];
    #pragma unroll
    for (int m = 4; m < 16; m += 4) {
        v0 = fmaf(hgv[m],   w[16 + m], v0);
        v1 = fmaf(hgv[m+1], w[17 + m], v1);
        v2 = fmaf(hgv[m+2], w[18 + m], v2);
        v3 = fmaf(hgv[m+3], w[19 + m], v3);
    }
    float s = sigm((v0 + v1) + (v2 + v3));
    float rh = s * hg;     // meaningful in lo lanes (r*hg)

    // rh exchange: lo lanes hold rh[0..15]; all lanes read the full set
    float rhv[16];
    sts_f32(rhslot, rh);
    lds_v4(rhv + 0,  rhb);
    lds_v4(rhv + 4,  rhb + 16);
    lds_v4(rhv + 8,  rhb + 32);
    lds_v4(rhv + 12, rhb + 48);

    // hc = tanh(K5 full dot + u4), 4 chains, u4 folded
    float p0 = fmaf(rhv[0], w[32], w[50]);
    float p1 = rhv[1]*w[33];
    float p2 = rhv[2]*w[34];
    float p3 = rhv[3]*w[35];
    #pragma unroll
    for (int m = 4; m < 16; m += 4) {
        p0 = fmaf(rhv[m],   w[32 + m], p0);
        p1 = fmaf(rhv[m+1], w[33 + m], p1);
        p2 = fmaf(rhv[m+2], w[34 + m], p2);
        p3 = fmaf(rhv[m+3], w[35 + m], p3);
    }
    float hc = tanha((p0 + p1) + (p2 + p3));
    float hn = fmaf(s, hg - hc, hc);   // correct in hi lanes (s = z)

    // h exchange: read full h from hi-lane copies (hbuf[16..31])
    sts_f32(hslot, hn);
    lds_v4(hv + 0,  hb + 64);
    lds_v4(hv + 4,  hb + 80);
    lds_v4(hv + 8,  hb + 96);
    lds_v4(hv + 12, hb + 112);

    // predicated store, off the critical chain
    st_pred(out + t * 16 + (threadIdx.x & 15), hn, hip);
}

#define LOADW(dst, slot)                                                     \
    {                                                                        \
        const float4* _s = &ring[(slot) * 416 + lane];                       \
        float4* _d = reinterpret_cast<float4*>(dst);                         \
        _Pragma("unroll")                                                    \
        for (int _j = 0; _j < 13; _j++) _d[_j] = _s[_j * 32];                \
    }

__global__ void __launch_bounds__(128) recurrent_kernel(float* __restrict__ out)
{
    __shared__ float4 ring[RING * 416];          // 6*416*16 = 39936 B
    __shared__ __align__(16) float hgbuf[16];
    __shared__ __align__(16) float rhbuf[32];
    __shared__ __align__(16) float hbuf[32];
    __shared__ int Wsh;
    __shared__ int cons_prog;

    int tid = threadIdx.x;
    if (tid == 0) { Wsh = 0; cons_prog = 0; }
    __syncthreads();

    int w = tid >> 5, lane = tid & 31;

    if (w == 0) {
        // ---------------- consumer ----------------
        uint32_t hip = (lane >= 16) ? 1u : 0u;
        uint32_t hgb = (uint32_t)__cvta_generic_to_shared(hgbuf);
        uint32_t hgslot = hgb + ((uint32_t)(lane & 15) << 2);
        uint32_t rhb = (uint32_t)__cvta_generic_to_shared(rhbuf);
        uint32_t rhslot = rhb + ((uint32_t)lane << 2);
        uint32_t hb  = (uint32_t)__cvta_generic_to_shared(hbuf);
        uint32_t hslot = hb + ((uint32_t)lane << 2);

        float hv[16];
        #pragma unroll
        for (int j = 0; j < 16; j++) hv[j] = 0.0f;

        uint32_t Wa = (uint32_t)__cvta_generic_to_shared(&Wsh);
        int Wloc = 0;

        float wa[52], wb[52];
        while (Wloc < 1) Wloc = ldacq(Wa);
        LOADW(wa, 0);

        int s1 = 1, s2 = 2;   // ring slots for t+1, t+2 (mod RING, incremental)
        #pragma unroll 1
        for (int t = 0; t < T_STEPS; t += 2) {
            // poll for t+1 data (demand no earlier than needed)
            while (Wloc < t + 2) Wloc = ldacq(Wa);
            LOADW(wb, s1);

            gru_step(wa, hv, out, t, hip, hgb, hgslot, rhb, rhslot, hb, hslot);

            // poll for t+2 data at the midpoint (after step t's compute)
            if (t + 2 < T_STEPS) {
                while (Wloc < t + 3) Wloc = ldacq(Wa);
                LOADW(wa, s2);
            }

            gru_step(wb, hv, out, t + 1, hip, hgb, hgslot, rhb, rhslot, hb, hslot);

            // all lanes store same value to same address: no divergence
            *(volatile int*)&cons_prog = t + 2;

            s1 += 2; if (s1 >= RING) s1 -= RING;
            s2 += 2; if (s2 >= RING) s2 -= RING;
        }
    } else if (w == 1) {
        // ---------------- producer (single warp, monotonic watermark) ----
        // wait_group 2 lag: publish t-1 after commit t.
        // RING=6 check: consumer mid-poll at t needs W>=t+3 <- producer t+4
        // <- waits cons_prog >= t-1; consumer published t at end of iter t-2.
        uint32_t ringb = (uint32_t)__cvta_generic_to_shared(ring);
        uint32_t Wa = (uint32_t)__cvta_generic_to_shared(&Wsh);
        const float4* blob4 = reinterpret_cast<const float4*>(g_blob);

        int ps = 0;
        for (int t = 0; t < T_STEPS; t++) {
            if (t >= RING) {
                while (*(volatile int*)&cons_prog < t - RING + 1) __nanosleep(32);
            }
            const float4* src = blob4 + (size_t)t * 416 + lane;
            uint32_t dst = ringb + ((uint32_t)ps * 416 + lane) * 16;
            #pragma unroll
            for (int j = 0; j < 13; j++) {
                asm volatile("cp.async.cg.shared.global [%0], [%1], 16;"
                             :: "r"(dst + j * 512), "l"(src + j * 32) : "memory");
            }
            asm volatile("cp.async.commit_group;" ::: "memory");
            asm volatile("cp.async.wait_group 2;" ::: "memory");
            __threadfence_block();
            __syncwarp();
            if (lane == 0 && t >= 2) {
                asm volatile("st.release.cta.shared::cta.b32 [%0], %1;"
                             :: "r"(Wa), "r"(t - 1) : "memory");
            }
            ps++; if (ps == RING) ps = 0;
        }
        asm volatile("cp.async.wait_group 0;" ::: "memory");
        __threadfence_block();
        __syncwarp();
        if (lane == 0) {
            asm volatile("st.release.cta.shared::cta.b32 [%0], %1;"
                         :: "r"(Wa), "r"(T_STEPS + RING) : "memory");
        }
    } else if (w == 2) {
        // ---------------- L2 prefetcher ----------------
        const char* p = reinterpret_cast<const char*>(g_blob);
        size_t total = (size_t)T_STEPS * 6656;
        #pragma unroll 4
        for (size_t off = (size_t)lane * 128; off < total; off += 4096) {
            asm volatile("prefetch.global.L2 [%0];" :: "l"(p + off));
        }
    }
}

extern "C" void kernel_launch(void* const* d_in, const int* in_sizes, int n_in,
                              void* d_out, int out_size)
{
    const float* inputs = (const float*)d_in[0];
    const float* a_list = (const float*)d_in[1];
    const float* gcn_wx = (const float*)d_in[2];
    const float* gcn_bx = (const float*)d_in[3];
    const float* gcn_wh = (const float*)d_in[4];
    const float* gcn_bh = (const float*)d_in[5];
    const float* gru_k  = (const float*)d_in[6];
    const float* gru_b  = (const float*)d_in[7];

    precompute_kernel<<<4096, 128>>>(inputs, a_list, gcn_wx, gcn_bx,
                                     gcn_wh, gcn_bh, gru_k, gru_b);
    recurrent_kernel<<<1, 128>>>((float*)d_out);
}